// round 13
// baseline (speedup 1.0000x reference)
#include <cuda_runtime.h>
#include <cuda_bf16.h>
#include <math.h>
#include <stdint.h>

// Problem constants (fixed shapes from reference setup_inputs)
#define CB      1024      // n_embd
#define NH      16        // heads
#define DH      64        // head dim
#define TT      4096      // seq len
#define BBATCH  2         // batch
#define WINDOW  256
#define STRIDE  128
#define NGLOB   16

#define MTOT    (BBATCH*TT)          // 8192
#define N_QKV   (3*CB)               // 3072

// ---------------------------------------------------------------------------
// Scratch (device globals: allocation-free per harness rules)
// ---------------------------------------------------------------------------
__device__ float g_q [BBATCH*NH*TT*DH];   // [b,h,t,d] fp32
__device__ float g_k [BBATCH*NH*TT*DH];   // fp32 (diagonal path)
__device__ float g_v [BBATCH*NH*TT*DH];   // fp32 (diagonal path)

__device__ __align__(128) __nv_bfloat16 g_khi[BBATCH*NH*TT*DH];
__device__ __align__(128) __nv_bfloat16 g_klo[BBATCH*NH*TT*DH];
__device__ __align__(128) __nv_bfloat16 g_vhi[BBATCH*NH*TT*DH];
__device__ __align__(128) __nv_bfloat16 g_vlo[BBATCH*NH*TT*DH];

__device__ __align__(128) __nv_bfloat16 g_xhi[MTOT*CB];     // bf16-hi of x
__device__ __align__(128) __nv_bfloat16 g_xlo[MTOT*CB];     // bf16-lo of x
__device__ __align__(128) __nv_bfloat16 g_yhi[MTOT*CB];     // written by attn3
__device__ __align__(128) __nv_bfloat16 g_ylo[MTOT*CB];
__device__ __align__(128) __nv_bfloat16 g_wqT_hi[N_QKV*CB]; // w_qkv^T [N,K]
__device__ __align__(128) __nv_bfloat16 g_wqT_lo[N_QKV*CB];
__device__ __align__(128) __nv_bfloat16 g_wpT_hi[CB*CB];    // w_proj^T [N,K]
__device__ __align__(128) __nv_bfloat16 g_wpT_lo[CB*CB];

// ---------------------------------------------------------------------------
// PTX helpers (all sm_80+ portable: cp.async / ldmatrix / mma.sync)
// ---------------------------------------------------------------------------
__device__ __forceinline__ uint32_t su32(const void* p) {
    return (uint32_t)__cvta_generic_to_shared(p);
}
__device__ __forceinline__ void cpa16(uint32_t s, const void* g) {
    asm volatile("cp.async.cg.shared.global [%0], [%1], 16;\n" :: "r"(s), "l"(g));
}
__device__ __forceinline__ void cpa_commit() {
    asm volatile("cp.async.commit_group;\n" ::);
}
template <int NW> __device__ __forceinline__ void cpa_wait() {
    asm volatile("cp.async.wait_group %0;\n" :: "n"(NW));
}
__device__ __forceinline__ void ldm_x4(uint32_t* r, uint32_t addr) {
    asm volatile("ldmatrix.sync.aligned.m8n8.x4.shared.b16 {%0,%1,%2,%3}, [%4];"
                 : "=r"(r[0]), "=r"(r[1]), "=r"(r[2]), "=r"(r[3]) : "r"(addr));
}
__device__ __forceinline__ void ldm_x4t(uint32_t* r, uint32_t addr) {
    asm volatile("ldmatrix.sync.aligned.m8n8.x4.trans.shared.b16 {%0,%1,%2,%3}, [%4];"
                 : "=r"(r[0]), "=r"(r[1]), "=r"(r[2]), "=r"(r[3]) : "r"(addr));
}
__device__ __forceinline__ void ldm_x2(uint32_t* r, uint32_t addr) {
    asm volatile("ldmatrix.sync.aligned.m8n8.x2.shared.b16 {%0,%1}, [%2];"
                 : "=r"(r[0]), "=r"(r[1]) : "r"(addr));
}
__device__ __forceinline__ void mma16816(float* c, const uint32_t* a, const uint32_t* b) {
    asm volatile("mma.sync.aligned.m16n8k16.row.col.f32.bf16.bf16.f32 "
                 "{%0,%1,%2,%3}, {%4,%5,%6,%7}, {%8,%9}, {%0,%1,%2,%3};"
                 : "+f"(c[0]), "+f"(c[1]), "+f"(c[2]), "+f"(c[3])
                 : "r"(a[0]), "r"(a[1]), "r"(a[2]), "r"(a[3]), "r"(b[0]), "r"(b[1]));
}
__device__ __forceinline__ __nv_bfloat16 bf_hi(float x) { return __float2bfloat16_rn(x); }

// ---------------------------------------------------------------------------
// Preprocessing: bf16 hi/lo splits and transpose-splits
// ---------------------------------------------------------------------------
__global__ void split_x(const float4* __restrict__ src) {
    int i = blockIdx.x * blockDim.x + threadIdx.x;   // MTOT*CB/4 threads
    float4 v = src[i];
    __nv_bfloat162 h01, h23, l01, l23;
    h01.x = bf_hi(v.x); l01.x = bf_hi(v.x - __bfloat162float(h01.x));
    h01.y = bf_hi(v.y); l01.y = bf_hi(v.y - __bfloat162float(h01.y));
    h23.x = bf_hi(v.z); l23.x = bf_hi(v.z - __bfloat162float(h23.x));
    h23.y = bf_hi(v.w); l23.y = bf_hi(v.w - __bfloat162float(h23.y));
    ((__nv_bfloat162*)g_xhi)[2 * i]     = h01;
    ((__nv_bfloat162*)g_xhi)[2 * i + 1] = h23;
    ((__nv_bfloat162*)g_xlo)[2 * i]     = l01;
    ((__nv_bfloat162*)g_xlo)[2 * i + 1] = l23;
}
// W [K,N] row-major -> WT_hi/WT_lo [N,K] bf16
template <int SEL>
__global__ void transpose_split(const float* __restrict__ W, int K, int N) {
    __nv_bfloat16* Thi = (SEL == 0) ? g_wqT_hi : g_wpT_hi;
    __nv_bfloat16* Tlo = (SEL == 0) ? g_wqT_lo : g_wpT_lo;
    __shared__ float t[32][33];
    const int n0 = blockIdx.x * 32, k0 = blockIdx.y * 32;
    const int tx = threadIdx.x, ty = threadIdx.y;
    #pragma unroll
    for (int r = ty; r < 32; r += 8)
        t[r][tx] = W[(size_t)(k0 + r) * N + n0 + tx];
    __syncthreads();
    #pragma unroll
    for (int r = ty; r < 32; r += 8) {
        float v = t[tx][r];
        __nv_bfloat16 h = bf_hi(v);
        __nv_bfloat16 l = bf_hi(v - __bfloat162float(h));
        size_t o = (size_t)(n0 + r) * K + k0 + tx;
        Thi[o] = h;
        Tlo[o] = l;
    }
}

// ---------------------------------------------------------------------------
// bf16x3 tensor-core GEMM via mma.sync.m16n8k16. Single barrier per K-iter,
// CORRECT ordering: wait(own groups) -> __syncthreads() (publishes all
// threads' cp.async completions; cp.async.wait_group is thread-local!) ->
// prefetch -> compute. The R9 'sync-then-wait' ordering was the NaN bug.
// MODE 1 epilogue: q/k/v fp32 + k/v bf16 hi/lo (for HMMA attention).
// ---------------------------------------------------------------------------
#define ST_BYTES  32768                 // per stage: Ahi|Alo|Bhi|Blo, 8KB each
#define TG_SMEM   (3*ST_BYTES)

template <int MODE>
__global__ void __launch_bounds__(256, 2)
tgemm(const float* __restrict__ bias, float* __restrict__ C, int N, int K)
{
    extern __shared__ __align__(128) unsigned char smbuf[];
    const uint32_t sbase = su32(smbuf);
    const int tid = threadIdx.x;
    const int bm = blockIdx.y * 128;
    const int bn = blockIdx.x * 128;

    const __nv_bfloat16* __restrict__ Ahi = (MODE == 1) ? g_xhi : g_yhi;
    const __nv_bfloat16* __restrict__ Alo = (MODE == 1) ? g_xlo : g_ylo;
    const __nv_bfloat16* __restrict__ Bhi = (MODE == 1) ? g_wqT_hi : g_wpT_hi;
    const __nv_bfloat16* __restrict__ Blo = (MODE == 1) ? g_wqT_lo : g_wpT_lo;

    const int NK = K / 32;   // 32

    const int ldrow = tid >> 1;
    const int ldc0  = (tid & 1) * 2;
    auto load_stage = [&](int stage, int k0) {
        const uint32_t sb = sbase + (uint32_t)stage * ST_BYTES;
        #pragma unroll
        for (int cc = 0; cc < 2; cc++) {
            const int c = ldc0 + cc;
            const uint32_t so = (uint32_t)(ldrow * 64 + ((c ^ ((ldrow >> 1) & 3)) << 4));
            const size_t ga = (size_t)(bm + ldrow) * K + k0 + c * 8;
            const size_t gb = (size_t)(bn + ldrow) * K + k0 + c * 8;
            cpa16(sb + so,               Ahi + ga);
            cpa16(sb + 8192 + so,        Alo + ga);
            cpa16(sb + 16384 + so,       Bhi + gb);
            cpa16(sb + 24576 + so,       Blo + gb);
        }
        cpa_commit();
    };

    load_stage(0, 0);
    load_stage(1, 32);

    const int lane = tid & 31, w = tid >> 5;
    const int wm = w >> 2, wn = w & 3;
    const int a_r = lane & 15, a_c = lane >> 4;
    const int b_r = lane & 7,  b_c = (lane >> 3) & 1;

    float acc[4][4][4];
    #pragma unroll
    for (int mt = 0; mt < 4; mt++)
        #pragma unroll
        for (int nt = 0; nt < 4; nt++)
            #pragma unroll
            for (int q = 0; q < 4; q++) acc[mt][nt][q] = 0.f;

    for (int ks = 0; ks < NK; ks++) {
        if (ks + 1 < NK) cpa_wait<1>(); else cpa_wait<0>();   // own groups for stage ks done
        __syncthreads();   // publish all threads' completions + WAR for prefetch target
        if (ks + 2 < NK) load_stage((ks + 2) % 3, (ks + 2) * 32);

        const uint32_t sb = sbase + (uint32_t)(ks % 3) * ST_BYTES;
        #pragma unroll
        for (int t = 0; t < 2; t++) {
            uint32_t bh[4][2], bl[4][2];
            #pragma unroll
            for (int nt = 0; nt < 4; nt++) {
                const int r = wn * 32 + nt * 8 + b_r;
                const int c = t * 2 + b_c;
                const uint32_t so = (uint32_t)(r * 64 + ((c ^ ((r >> 1) & 3)) << 4));
                ldm_x2(bh[nt], sb + 16384 + so);
                ldm_x2(bl[nt], sb + 24576 + so);
            }
            #pragma unroll
            for (int mt = 0; mt < 4; mt++) {
                uint32_t ah[4], al[4];
                const int r = wm * 64 + mt * 16 + a_r;
                const int c = t * 2 + a_c;
                const uint32_t so = (uint32_t)(r * 64 + ((c ^ ((r >> 1) & 3)) << 4));
                ldm_x4(ah, sb + so);
                ldm_x4(al, sb + 8192 + so);
                #pragma unroll
                for (int nt = 0; nt < 4; nt++) {
                    mma16816(acc[mt][nt], ah, bh[nt]);
                    mma16816(acc[mt][nt], ah, bl[nt]);
                    mma16816(acc[mt][nt], al, bh[nt]);
                }
            }
        }
    }

    const int colq = (lane & 3) * 2;
    const int rowq = lane >> 2;
    #pragma unroll
    for (int nt = 0; nt < 4; nt++) {
        const int cg = bn + wn * 32 + nt * 8 + colq;
        const float b0 = bias[cg], b1 = bias[cg + 1];
        #pragma unroll
        for (int mt = 0; mt < 4; mt++) {
            const int r0 = bm + wm * 64 + mt * 16 + rowq;
            const int r1 = r0 + 8;
            float v00 = acc[mt][nt][0] + b0, v01 = acc[mt][nt][1] + b1;
            float v10 = acc[mt][nt][2] + b0, v11 = acc[mt][nt][3] + b1;
            if (MODE == 0) {
                *(float2*)(C + (size_t)r0 * N + cg) = make_float2(v00, v01);
                *(float2*)(C + (size_t)r1 * N + cg) = make_float2(v10, v11);
            } else {
                const int sec = cg >> 10;            // 0=q,1=k,2=v
                const int f  = cg & 1023;
                const int hh = f >> 6, d0 = f & 63;  // d0 even
                #pragma unroll
                for (int rr = 0; rr < 2; rr++) {
                    const int mrow = rr ? r1 : r0;
                    const float va = rr ? v10 : v00;
                    const float vb = rr ? v11 : v01;
                    const int bidx = mrow >> 12;
                    const int ttk  = mrow & (TT - 1);
                    const int bh2  = bidx * NH + hh;
                    const size_t base = ((size_t)bh2 * TT + ttk) * DH + d0;
                    if (sec == 0) {
                        *(float2*)(g_q + base) = make_float2(va, vb);
                    } else {
                        float* dst = (sec == 1) ? g_k : g_v;
                        *(float2*)(dst + base) = make_float2(va, vb);
                        __nv_bfloat162 h2, l2;
                        h2.x = bf_hi(va); h2.y = bf_hi(vb);
                        l2.x = bf_hi(va - __bfloat162float(h2.x));
                        l2.y = bf_hi(vb - __bfloat162float(h2.y));
                        __nv_bfloat162* dh = (sec == 1) ? (__nv_bfloat162*)g_khi
                                                        : (__nv_bfloat162*)g_vhi;
                        __nv_bfloat162* dl = (sec == 1) ? (__nv_bfloat162*)g_klo
                                                        : (__nv_bfloat162*)g_vlo;
                        dh[base >> 1] = h2;
                        dl[base >> 1] = l2;
                    }
                }
            }
        }
    }
}

// ---------------------------------------------------------------------------
// HMMA flash sparse attention v3.2.
// Window/global blocks: 2 syncs/block with CORRECT pipeline ordering
// (wait own groups -> sync publishes completions -> prefetch -> compute).
// Local-max softmax with per-warp correction factors folded into the P pack,
// m/l ping-ponged by block parity. Diag levels: global K/V reads, top sync
// per level (stats ordering). Epilogue writes y directly as bf16 hi/lo.
// ---------------------------------------------------------------------------
#define AT_QHI   0
#define AT_QLO   8192
#define AT_KV    16384                 // 2 bufs x 32KB
#define AT_MRG   AT_KV                 // merge buffer reuses KV area (16KB)
#define AT_STAT  (AT_KV + 65536)       // 81920
#define ATTN3_SMEM (AT_STAT + 768*4)   // stm/stl/pmx/psm/dal/dpp: 768 floats

__global__ void __launch_bounds__(256, 2)
attn3()
{
    extern __shared__ __align__(16) unsigned char smb[];
    const uint32_t sb = su32(smb);
    float* stm = (float*)(smb + AT_STAT);    // [2][64] running max (parity)
    float* stl = stm + 128;                  // [2][64] running sum (parity)
    float* pmx = stm + 256;                  // [2][64] per-kg raw max
    float* psm = stm + 384;                  // [2][64] per-kg partial sum
    float* dal = stm + 512;                  // [2][64] diag alpha (parity)
    float* dpp = stm + 640;                  // [2][64] diag p (parity)

    const int tid  = threadIdx.x;
    const int lane = tid & 31;
    const int w    = tid >> 5;
    const int qg   = w >> 1, kg = w & 1;
    const int rbase = qg * 16;
    const int colbase = kg * 32;
    const int q0 = blockIdx.x * 64;
    const int h  = blockIdx.y;
    const int b  = blockIdx.z;
    const int bh = b * NH + h;

    // ---- load Q fp32 -> bf16 hi/lo smem tiles (chunk-swizzled) ----
    {
        const float* qsrc = g_q + ((size_t)bh * TT + q0) * DH;
        #pragma unroll
        for (int it = 0; it < 2; it++) {
            const int id = tid + it * 256;       // 0..511
            const int row = id >> 3, c = id & 7;
            const float4 f0 = *(const float4*)(qsrc + (size_t)row * DH + c * 8);
            const float4 f1 = *(const float4*)(qsrc + (size_t)row * DH + c * 8 + 4);
            float vv[8] = {f0.x, f0.y, f0.z, f0.w, f1.x, f1.y, f1.z, f1.w};
            __nv_bfloat162 hh[4], ll[4];
            #pragma unroll
            for (int u = 0; u < 4; u++) {
                hh[u].x = bf_hi(vv[2*u]);   hh[u].y = bf_hi(vv[2*u+1]);
                ll[u].x = bf_hi(vv[2*u]   - __bfloat162float(hh[u].x));
                ll[u].y = bf_hi(vv[2*u+1] - __bfloat162float(hh[u].y));
            }
            const uint32_t off = (uint32_t)(row * 128 + ((c ^ (row & 7)) << 4));
            *(uint4*)(smb + AT_QHI + off) = *(uint4*)hh;
            *(uint4*)(smb + AT_QLO + off) = *(uint4*)ll;
        }
        if (tid < 64) { stm[tid] = -INFINITY; stl[tid] = 0.f; }
    }

    // ---- window/global block schedule ----
    const int kstart = (q0 > 256) ? (q0 - 256) : 0;
    const int extra  = (kstart > 0) ? 1 : 0;
    const int nb     = extra + (q0 + 64 - kstart) / 64;
    const int ndiag  = (q0 / 128 >= 3) ? (q0 / 128 - 2) : 0;   // levels s=3..
    auto kb_of = [&](int bi) -> int {
        return (extra && bi == 0) ? 0 : kstart + (bi - extra) * 64;
    };

    auto load_kv = [&](int bufn, int kb) {
        const size_t gb = ((size_t)bh * TT + kb) * DH;
        const __nv_bfloat16* srcs[4] = {g_khi + gb, g_klo + gb, g_vhi + gb, g_vlo + gb};
        const uint32_t dst0 = sb + AT_KV + (uint32_t)bufn * 32768;
        #pragma unroll
        for (int qq = 0; qq < 8; qq++) {
            const int tile = qq >> 1;
            const int within = tid + (qq & 1) * 256;   // 0..511
            const int row = within >> 3, c = within & 7;
            cpa16(dst0 + tile * 8192 + row * 128 + ((c ^ (row & 7)) << 4),
                  srcs[tile] + (size_t)row * DH + c * 8);
        }
        cpa_commit();
    };

    load_kv(0, kb_of(0));

    float o[8][4];
    #pragma unroll
    for (int nt = 0; nt < 8; nt++)
        #pragma unroll
        for (int e = 0; e < 4; e++) o[nt][e] = 0.f;

    const int quad_lo = (lane >> 3) & 1;
    const int quad_hi = lane >> 4;
    const int l7 = lane & 7;
    const int rl = rbase + (lane >> 2);    // fragment low row

    int par = 0;

    for (int bi = 0; bi < nb; bi++) {
        const int kb  = kb_of(bi);
        const int buf = bi & 1;
        const bool gonly = (extra && bi == 0);

        cpa_wait<0>();      // own copies for block bi complete
        __syncthreads();    // publish all threads' completions + WAR + stats order
        if (bi + 1 < nb) load_kv(buf ^ 1, kb_of(bi + 1));   // prefetch next block

        const uint32_t kvb = sb + AT_KV + (uint32_t)buf * 32768;

        // ---- scores: S[16q x 32k] per warp, bf16x3 ----
        float s[4][4];
        #pragma unroll
        for (int nt = 0; nt < 4; nt++)
            #pragma unroll
            for (int e = 0; e < 4; e++) s[nt][e] = 0.f;

        #pragma unroll
        for (int ks = 0; ks < 4; ks++) {
            uint32_t qh[4], ql[4];
            {
                const int row = rbase + quad_lo * 8 + l7;
                const int ch  = 2 * ks + quad_hi;
                const uint32_t off = (uint32_t)(row * 128 + ((ch ^ (row & 7)) << 4));
                ldm_x4(qh, sb + AT_QHI + off);
                ldm_x4(ql, sb + AT_QLO + off);
            }
            #pragma unroll
            for (int ntp = 0; ntp < 2; ntp++) {
                uint32_t kh[4], kl[4];
                const int rowk = colbase + ntp * 16 + quad_hi * 8 + l7;
                const int chk  = 2 * ks + quad_lo;
                const uint32_t offk = (uint32_t)(rowk * 128 + ((chk ^ (rowk & 7)) << 4));
                ldm_x4(kh, kvb + offk);
                ldm_x4(kl, kvb + 8192 + offk);
                mma16816(s[2*ntp],   qh, kh);
                mma16816(s[2*ntp],   qh, kl);
                mma16816(s[2*ntp],   ql, kh);
                mma16816(s[2*ntp+1], qh, kh + 2);
                mma16816(s[2*ntp+1], qh, kl + 2);
                mma16816(s[2*ntp+1], ql, kh + 2);
            }
        }

        // ---- mask + scale ----
        #pragma unroll
        for (int nt = 0; nt < 4; nt++)
            #pragma unroll
            for (int e = 0; e < 4; e++) {
                const int row = rl + (e >> 1) * 8;
                const int i = q0 + row;
                const int j = kb + colbase + nt * 8 + 2 * (lane & 3) + (e & 1);
                const int dij = i - j;
                const bool ok = gonly ? (j < NGLOB)
                    : (dij >= 0 && (dij < WINDOW || (dij & (STRIDE - 1)) == 0 || j < NGLOB));
                s[nt][e] = ok ? s[nt][e] * 0.125f : -INFINITY;
            }

        // ---- per-warp raw max over own 32 cols ----
        float mx0 = fmaxf(fmaxf(s[0][0], s[0][1]), fmaxf(s[1][0], s[1][1]));
        mx0 = fmaxf(mx0, fmaxf(fmaxf(s[2][0], s[2][1]), fmaxf(s[3][0], s[3][1])));
        float mx1 = fmaxf(fmaxf(s[0][2], s[0][3]), fmaxf(s[1][2], s[1][3]));
        mx1 = fmaxf(mx1, fmaxf(fmaxf(s[2][2], s[2][3]), fmaxf(s[3][2], s[3][3])));
        mx0 = fmaxf(mx0, __shfl_xor_sync(0xffffffffu, mx0, 1));
        mx0 = fmaxf(mx0, __shfl_xor_sync(0xffffffffu, mx0, 2));
        mx1 = fmaxf(mx1, __shfl_xor_sync(0xffffffffu, mx1, 1));
        mx1 = fmaxf(mx1, __shfl_xor_sync(0xffffffffu, mx1, 2));
        const float mx0c = fmaxf(mx0, -1e30f);
        const float mx1c = fmaxf(mx1, -1e30f);

        // ---- local exp vs own max + partial sums ----
        float sum0 = 0.f, sum1 = 0.f;
        #pragma unroll
        for (int nt = 0; nt < 4; nt++) {
            s[nt][0] = __expf(s[nt][0] - mx0c); sum0 += s[nt][0];
            s[nt][1] = __expf(s[nt][1] - mx0c); sum0 += s[nt][1];
            s[nt][2] = __expf(s[nt][2] - mx1c); sum1 += s[nt][2];
            s[nt][3] = __expf(s[nt][3] - mx1c); sum1 += s[nt][3];
        }
        sum0 += __shfl_xor_sync(0xffffffffu, sum0, 1);
        sum0 += __shfl_xor_sync(0xffffffffu, sum0, 2);
        sum1 += __shfl_xor_sync(0xffffffffu, sum1, 1);
        sum1 += __shfl_xor_sync(0xffffffffu, sum1, 2);
        if ((lane & 3) == 0) {
            pmx[kg * 64 + rl]     = mx0;   psm[kg * 64 + rl]     = sum0;
            pmx[kg * 64 + rl + 8] = mx1;   psm[kg * 64 + rl + 8] = sum1;
        }
        __syncthreads();

        // ---- global merge (redundant per warp) ----
        const float mo0 = stm[par * 64 + rl], mo1 = stm[par * 64 + rl + 8];
        const float xa0 = pmx[rl],     xb0 = pmx[64 + rl];
        const float xa1 = pmx[rl + 8], xb1 = pmx[64 + rl + 8];
        const float mn0 = fmaxf(mo0, fmaxf(xa0, xb0));
        const float mn1 = fmaxf(mo1, fmaxf(xa1, xb1));
        const float al0 = __expf(mo0 - mn0);
        const float al1 = __expf(mo1 - mn1);
        const float f0  = __expf(mx0c - mn0);   // this warp's correction
        const float f1  = __expf(mx1c - mn1);
        if (kg == 0 && (lane & 3) == 0) {
            const float ga0 = __expf(fmaxf(xa0, -1e30f) - mn0);
            const float gb0 = __expf(fmaxf(xb0, -1e30f) - mn0);
            const float ga1 = __expf(fmaxf(xa1, -1e30f) - mn1);
            const float gb1 = __expf(fmaxf(xb1, -1e30f) - mn1);
            stm[(par ^ 1) * 64 + rl]     = mn0;
            stm[(par ^ 1) * 64 + rl + 8] = mn1;
            stl[(par ^ 1) * 64 + rl]     = stl[par * 64 + rl]     * al0 + psm[rl]     * ga0 + psm[64 + rl]     * gb0;
            stl[(par ^ 1) * 64 + rl + 8] = stl[par * 64 + rl + 8] * al1 + psm[rl + 8] * ga1 + psm[64 + rl + 8] * gb1;
        }

        // ---- rescale O ----
        #pragma unroll
        for (int nt = 0; nt < 8; nt++) {
            o[nt][0] *= al0; o[nt][1] *= al0;
            o[nt][2] *= al1; o[nt][3] *= al1;
        }

        // ---- PV: P (x f_own, hi/lo) x V (hi/lo), 3 combos ----
        #pragma unroll
        for (int ks2 = 0; ks2 < 2; ks2++) {
            const int t0 = 2 * ks2, t1 = t0 + 1;
            uint32_t pah[4], pal[4];
            {
                __nv_bfloat162 h2, l2;
                #pragma unroll
                for (int u = 0; u < 4; u++) {
                    const int tt = (u < 2) ? t0 : t1;
                    const int e0 = (u & 1) * 2;
                    const float fe = (u & 1) ? f1 : f0;
                    const float p0 = s[tt][e0] * fe, p1 = s[tt][e0 + 1] * fe;
                    h2.x = bf_hi(p0); h2.y = bf_hi(p1);
                    l2.x = bf_hi(p0 - __bfloat162float(h2.x));
                    l2.y = bf_hi(p1 - __bfloat162float(h2.y));
                    pah[u] = *(uint32_t*)&h2;
                    pal[u] = *(uint32_t*)&l2;
                }
            }
            const int kb2 = colbase + ks2 * 16;
            #pragma unroll
            for (int ntp = 0; ntp < 4; ntp++) {
                uint32_t vh[4], vl[4];
                const int rowv = kb2 + quad_lo * 8 + l7;
                const int chv  = 2 * ntp + quad_hi;
                const uint32_t offv = (uint32_t)(rowv * 128 + ((chv ^ (rowv & 7)) << 4));
                ldm_x4t(vh, kvb + 16384 + offv);
                ldm_x4t(vl, kvb + 24576 + offv);
                mma16816(o[2*ntp],   pah, vh);
                mma16816(o[2*ntp],   pah, vl);
                mma16816(o[2*ntp],   pal, vh);
                mma16816(o[2*ntp+1], pah, vh + 2);
                mma16816(o[2*ntp+1], pah, vl + 2);
                mma16816(o[2*ntp+1], pal, vh + 2);
            }
        }
        par ^= 1;
    }

    // ---- diagonal far-stride levels: global K/V, top sync per level ----
    for (int lev = 0; lev < ndiag; lev++) {
        // Orders this level's stm/stl[par] reads after the previous
        // block's/level's writer-warp updates.
        __syncthreads();
        const int kb = q0 - 128 * (lev + 3);
        const int rowi = w * 8 + (lane >> 2);
        const int q = lane & 3;
        const int ws = par ^ 1;
        {
            const float* krow = g_k + ((size_t)bh * TT + kb + rowi) * DH + q * 16;
            float part = 0.f;
            #pragma unroll
            for (int i4 = 0; i4 < 4; i4++) {
                const float4 k4 = *(const float4*)(krow + i4 * 4);
                const int d0 = q * 16 + i4 * 4;
                const int c8 = d0 >> 3, sub = d0 & 7;
                const uint32_t qoff = (uint32_t)(rowi * 128 + ((c8 ^ (rowi & 7)) << 4) + sub * 2);
                const __nv_bfloat162 qh0 = *(const __nv_bfloat162*)(smb + AT_QHI + qoff);
                const __nv_bfloat162 qh1 = *(const __nv_bfloat162*)(smb + AT_QHI + qoff + 4);
                const __nv_bfloat162 ql0 = *(const __nv_bfloat162*)(smb + AT_QLO + qoff);
                const __nv_bfloat162 ql1 = *(const __nv_bfloat162*)(smb + AT_QLO + qoff + 4);
                part += (__bfloat162float(qh0.x) + __bfloat162float(ql0.x)) * k4.x;
                part += (__bfloat162float(qh0.y) + __bfloat162float(ql0.y)) * k4.y;
                part += (__bfloat162float(qh1.x) + __bfloat162float(ql1.x)) * k4.z;
                part += (__bfloat162float(qh1.y) + __bfloat162float(ql1.y)) * k4.w;
            }
            part += __shfl_xor_sync(0xffffffffu, part, 1);
            part += __shfl_xor_sync(0xffffffffu, part, 2);
            const int j = kb + rowi;
            const float sv = (j >= NGLOB) ? part * 0.125f : -INFINITY;
            if (q == 0) {
                const float mo = stm[par * 64 + rowi];
                const float mn = fmaxf(mo, sv);
                const float alpha = __expf(mo - mn);
                const float p = __expf(sv - mn);
                stm[ws * 64 + rowi] = mn;
                stl[ws * 64 + rowi] = stl[par * 64 + rowi] * alpha + p;
                dal[ws * 64 + rowi] = alpha;
                dpp[ws * 64 + rowi] = p;
            }
        }
        __syncthreads();
        const float al0 = dal[ws * 64 + rl], al1 = dal[ws * 64 + rl + 8];
        #pragma unroll
        for (int nt = 0; nt < 8; nt++) {
            o[nt][0] *= al0; o[nt][1] *= al0;
            o[nt][2] *= al1; o[nt][3] *= al1;
        }
        if (kg == 0) {
            #pragma unroll
            for (int rr = 0; rr < 2; rr++) {
                const int row = rl + rr * 8;
                const float p = dpp[ws * 64 + row];
                if (p != 0.f) {
                    const float* vrow = g_v + ((size_t)bh * TT + kb + row) * DH;
                    #pragma unroll
                    for (int nt = 0; nt < 8; nt++) {
                        const float2 vv = *(const float2*)(vrow + nt * 8 + 2 * (lane & 3));
                        o[nt][rr * 2 + 0] += p * vv.x;
                        o[nt][rr * 2 + 1] += p * vv.y;
                    }
                }
            }
        }
        par ^= 1;
    }

    // ---- merge partial O: kg0 keeps rows 0-7, kg1 keeps rows 8-15 ----
    __syncthreads();
    float* mrg = (float*)(smb + AT_MRG);   // [qg][16][64]
    {
        const int wr = (kg == 0) ? (lane >> 2) + 8 : (lane >> 2);
        float* basep = mrg + (qg * 16 + wr) * 64;
        const int c0 = kg ? 0 : 2;
        #pragma unroll
        for (int nt = 0; nt < 8; nt++) {
            basep[nt * 8 + 2 * (lane & 3)]     = o[nt][c0];
            basep[nt * 8 + 2 * (lane & 3) + 1] = o[nt][c0 + 1];
        }
    }
    __syncthreads();
    {
        const int rd = (kg == 0) ? (lane >> 2) : (lane >> 2) + 8;
        const float* basep = mrg + (qg * 16 + rd) * 64;
        const int c0 = kg ? 2 : 0;
        #pragma unroll
        for (int nt = 0; nt < 8; nt++) {
            o[nt][c0]     += basep[nt * 8 + 2 * (lane & 3)];
            o[nt][c0 + 1] += basep[nt * 8 + 2 * (lane & 3) + 1];
        }
    }

    // ---- normalize + write y as bf16 hi/lo (feeds projection GEMM) ----
    {
        const int ce0 = kg ? 2 : 0;
        const int row = rbase + (kg ? 8 : 0) + (lane >> 2);
        const float inv = 1.f / stl[par * 64 + row];
        const size_t ybase = ((size_t)(b * TT + q0 + row)) * CB + h * DH;
        #pragma unroll
        for (int nt = 0; nt < 8; nt++) {
            const float v0 = o[nt][ce0] * inv;
            const float v1 = o[nt][ce0 + 1] * inv;
            __nv_bfloat162 h2, l2;
            h2.x = bf_hi(v0); h2.y = bf_hi(v1);
            l2.x = bf_hi(v0 - __bfloat162float(h2.x));
            l2.y = bf_hi(v1 - __bfloat162float(h2.y));
            const size_t idx = (ybase + nt * 8 + 2 * (lane & 3)) >> 1;
            ((__nv_bfloat162*)g_yhi)[idx] = h2;
            ((__nv_bfloat162*)g_ylo)[idx] = l2;
        }
    }
}

// ---------------------------------------------------------------------------
extern "C" void kernel_launch(void* const* d_in, const int* in_sizes, int n_in,
                              void* d_out, int out_size)
{
    (void)in_sizes; (void)n_in; (void)out_size;
    const float* x      = (const float*)d_in[0];
    const float* w_qkv  = (const float*)d_in[1];
    const float* b_qkv  = (const float*)d_in[2];
    const float* w_proj = (const float*)d_in[3];
    const float* b_proj = (const float*)d_in[4];
    float* out = (float*)d_out;

    cudaFuncSetAttribute(tgemm<1>, cudaFuncAttributeMaxDynamicSharedMemorySize, TG_SMEM);
    cudaFuncSetAttribute(tgemm<0>, cudaFuncAttributeMaxDynamicSharedMemorySize, TG_SMEM);
    cudaFuncSetAttribute(attn3,    cudaFuncAttributeMaxDynamicSharedMemorySize, ATTN3_SMEM);

    // 0) bf16 hi/lo splits of activations + transposed weight splits
    split_x<<<(MTOT * CB / 4) / 256, 256>>>((const float4*)x);
    transpose_split<0><<<dim3(N_QKV / 32, CB / 32), dim3(32, 8)>>>(w_qkv, CB, N_QKV);
    transpose_split<1><<<dim3(CB / 32, CB / 32), dim3(32, 8)>>>(w_proj, CB, CB);

    // 1) QKV GEMM -> q/k/v fp32 + k/v bf16 hi/lo
    tgemm<1><<<dim3(N_QKV / 128, MTOT / 128), 256, TG_SMEM>>>(b_qkv, nullptr, N_QKV, CB);

    // 2) HMMA flash sparse attention -> g_yhi/g_ylo (split fused)
    attn3<<<dim3(TT / 64, NH, BBATCH), 256, ATTN3_SMEM>>>();

    // 3) output projection GEMM -> d_out
    tgemm<0><<<dim3(CB / 128, MTOT / 128), 256, TG_SMEM>>>(b_proj, out, CB, CB);
}

// round 15
// speedup vs baseline: 1.4922x; 1.4922x over previous
#include <cuda_runtime.h>
#include <cuda_bf16.h>
#include <math.h>
#include <stdint.h>

// Problem constants (fixed shapes from reference setup_inputs)
#define CB      1024      // n_embd
#define NH      16        // heads
#define DH      64        // head dim
#define TT      4096      // seq len
#define BBATCH  2         // batch
#define WINDOW  256
#define STRIDE  128
#define NGLOB   16

#define MTOT    (BBATCH*TT)          // 8192
#define N_QKV   (3*CB)               // 3072

// ---------------------------------------------------------------------------
// Scratch (device globals: allocation-free per harness rules)
// ---------------------------------------------------------------------------
__device__ float g_q [BBATCH*NH*TT*DH];   // [b,h,t,d] fp32
__device__ float g_k [BBATCH*NH*TT*DH];   // fp32 (diagonal path)
__device__ float g_v [BBATCH*NH*TT*DH];   // fp32 (diagonal path)

__device__ __align__(128) __nv_bfloat16 g_khi[BBATCH*NH*TT*DH];
__device__ __align__(128) __nv_bfloat16 g_klo[BBATCH*NH*TT*DH];
__device__ __align__(128) __nv_bfloat16 g_vhi[BBATCH*NH*TT*DH];
__device__ __align__(128) __nv_bfloat16 g_vlo[BBATCH*NH*TT*DH];

__device__ __align__(128) __nv_bfloat16 g_xhi[MTOT*CB];     // bf16-hi of x
__device__ __align__(128) __nv_bfloat16 g_xlo[MTOT*CB];     // bf16-lo of x
__device__ __align__(128) __nv_bfloat16 g_yhi[MTOT*CB];     // written by attn3
__device__ __align__(128) __nv_bfloat16 g_ylo[MTOT*CB];
__device__ __align__(128) __nv_bfloat16 g_wqT_hi[N_QKV*CB]; // w_qkv^T [N,K]
__device__ __align__(128) __nv_bfloat16 g_wqT_lo[N_QKV*CB];
__device__ __align__(128) __nv_bfloat16 g_wpT_hi[CB*CB];    // w_proj^T [N,K]
__device__ __align__(128) __nv_bfloat16 g_wpT_lo[CB*CB];

// ---------------------------------------------------------------------------
// PTX helpers (all sm_80+ portable: cp.async / ldmatrix / mma.sync)
// ---------------------------------------------------------------------------
__device__ __forceinline__ uint32_t su32(const void* p) {
    return (uint32_t)__cvta_generic_to_shared(p);
}
__device__ __forceinline__ void cpa16(uint32_t s, const void* g) {
    asm volatile("cp.async.cg.shared.global [%0], [%1], 16;\n" :: "r"(s), "l"(g));
}
__device__ __forceinline__ void cpa_commit() {
    asm volatile("cp.async.commit_group;\n" ::);
}
template <int NW> __device__ __forceinline__ void cpa_wait() {
    asm volatile("cp.async.wait_group %0;\n" :: "n"(NW));
}
__device__ __forceinline__ void ldm_x4(uint32_t* r, uint32_t addr) {
    asm volatile("ldmatrix.sync.aligned.m8n8.x4.shared.b16 {%0,%1,%2,%3}, [%4];"
                 : "=r"(r[0]), "=r"(r[1]), "=r"(r[2]), "=r"(r[3]) : "r"(addr));
}
__device__ __forceinline__ void ldm_x4t(uint32_t* r, uint32_t addr) {
    asm volatile("ldmatrix.sync.aligned.m8n8.x4.trans.shared.b16 {%0,%1,%2,%3}, [%4];"
                 : "=r"(r[0]), "=r"(r[1]), "=r"(r[2]), "=r"(r[3]) : "r"(addr));
}
__device__ __forceinline__ void ldm_x2(uint32_t* r, uint32_t addr) {
    asm volatile("ldmatrix.sync.aligned.m8n8.x2.shared.b16 {%0,%1}, [%2];"
                 : "=r"(r[0]), "=r"(r[1]) : "r"(addr));
}
__device__ __forceinline__ void mma16816(float* c, const uint32_t* a, const uint32_t* b) {
    asm volatile("mma.sync.aligned.m16n8k16.row.col.f32.bf16.bf16.f32 "
                 "{%0,%1,%2,%3}, {%4,%5,%6,%7}, {%8,%9}, {%0,%1,%2,%3};"
                 : "+f"(c[0]), "+f"(c[1]), "+f"(c[2]), "+f"(c[3])
                 : "r"(a[0]), "r"(a[1]), "r"(a[2]), "r"(a[3]), "r"(b[0]), "r"(b[1]));
}
__device__ __forceinline__ __nv_bfloat16 bf_hi(float x) { return __float2bfloat16_rn(x); }

// ---------------------------------------------------------------------------
// Preprocessing: bf16 hi/lo splits and transpose-splits
// ---------------------------------------------------------------------------
__global__ void split_x(const float4* __restrict__ src) {
    int i = blockIdx.x * blockDim.x + threadIdx.x;   // MTOT*CB/4 threads
    float4 v = src[i];
    __nv_bfloat162 h01, h23, l01, l23;
    h01.x = bf_hi(v.x); l01.x = bf_hi(v.x - __bfloat162float(h01.x));
    h01.y = bf_hi(v.y); l01.y = bf_hi(v.y - __bfloat162float(h01.y));
    h23.x = bf_hi(v.z); l23.x = bf_hi(v.z - __bfloat162float(h23.x));
    h23.y = bf_hi(v.w); l23.y = bf_hi(v.w - __bfloat162float(h23.y));
    ((__nv_bfloat162*)g_xhi)[2 * i]     = h01;
    ((__nv_bfloat162*)g_xhi)[2 * i + 1] = h23;
    ((__nv_bfloat162*)g_xlo)[2 * i]     = l01;
    ((__nv_bfloat162*)g_xlo)[2 * i + 1] = l23;
}
// W [K,N] row-major -> WT_hi/WT_lo [N,K] bf16
template <int SEL>
__global__ void transpose_split(const float* __restrict__ W, int K, int N) {
    __nv_bfloat16* Thi = (SEL == 0) ? g_wqT_hi : g_wpT_hi;
    __nv_bfloat16* Tlo = (SEL == 0) ? g_wqT_lo : g_wpT_lo;
    __shared__ float t[32][33];
    const int n0 = blockIdx.x * 32, k0 = blockIdx.y * 32;
    const int tx = threadIdx.x, ty = threadIdx.y;
    #pragma unroll
    for (int r = ty; r < 32; r += 8)
        t[r][tx] = W[(size_t)(k0 + r) * N + n0 + tx];
    __syncthreads();
    #pragma unroll
    for (int r = ty; r < 32; r += 8) {
        float v = t[tx][r];
        __nv_bfloat16 h = bf_hi(v);
        __nv_bfloat16 l = bf_hi(v - __bfloat162float(h));
        size_t o = (size_t)(n0 + r) * K + k0 + tx;
        Thi[o] = h;
        Tlo[o] = l;
    }
}

// ---------------------------------------------------------------------------
// bf16x3 tensor-core GEMM via mma.sync.m16n8k16. PROVEN R8 structure:
// wait -> sync -> prefetch -> compute -> trailing sync. The trailing barrier
// is load-bearing for perf (keeps warps phase-locked -> dense HMMA issue;
// removing it measured +50% tensor-active cycles).
// MODE 1 epilogue: q/k/v fp32 + k/v bf16 hi/lo (for HMMA attention).
// ---------------------------------------------------------------------------
#define ST_BYTES  32768                 // per stage: Ahi|Alo|Bhi|Blo, 8KB each
#define TG_SMEM   (3*ST_BYTES)

template <int MODE>
__global__ void __launch_bounds__(256, 2)
tgemm(const float* __restrict__ bias, float* __restrict__ C, int N, int K)
{
    extern __shared__ __align__(128) unsigned char smbuf[];
    const uint32_t sbase = su32(smbuf);
    const int tid = threadIdx.x;
    const int bm = blockIdx.y * 128;
    const int bn = blockIdx.x * 128;

    const __nv_bfloat16* __restrict__ Ahi = (MODE == 1) ? g_xhi : g_yhi;
    const __nv_bfloat16* __restrict__ Alo = (MODE == 1) ? g_xlo : g_ylo;
    const __nv_bfloat16* __restrict__ Bhi = (MODE == 1) ? g_wqT_hi : g_wpT_hi;
    const __nv_bfloat16* __restrict__ Blo = (MODE == 1) ? g_wqT_lo : g_wpT_lo;

    const int NK = K / 32;   // 32

    const int ldrow = tid >> 1;
    const int ldc0  = (tid & 1) * 2;
    auto load_stage = [&](int stage, int k0) {
        const uint32_t sb = sbase + (uint32_t)stage * ST_BYTES;
        #pragma unroll
        for (int cc = 0; cc < 2; cc++) {
            const int c = ldc0 + cc;
            const uint32_t so = (uint32_t)(ldrow * 64 + ((c ^ ((ldrow >> 1) & 3)) << 4));
            const size_t ga = (size_t)(bm + ldrow) * K + k0 + c * 8;
            const size_t gb = (size_t)(bn + ldrow) * K + k0 + c * 8;
            cpa16(sb + so,               Ahi + ga);
            cpa16(sb + 8192 + so,        Alo + ga);
            cpa16(sb + 16384 + so,       Bhi + gb);
            cpa16(sb + 24576 + so,       Blo + gb);
        }
        cpa_commit();
    };

    load_stage(0, 0);
    load_stage(1, 32);

    const int lane = tid & 31, w = tid >> 5;
    const int wm = w >> 2, wn = w & 3;
    const int a_r = lane & 15, a_c = lane >> 4;
    const int b_r = lane & 7,  b_c = (lane >> 3) & 1;

    float acc[4][4][4];
    #pragma unroll
    for (int mt = 0; mt < 4; mt++)
        #pragma unroll
        for (int nt = 0; nt < 4; nt++)
            #pragma unroll
            for (int q = 0; q < 4; q++) acc[mt][nt][q] = 0.f;

    for (int ks = 0; ks < NK; ks++) {
        if (ks == NK - 1) cpa_wait<0>(); else cpa_wait<1>();
        __syncthreads();
        if (ks + 2 < NK) load_stage((ks + 2) % 3, (ks + 2) * 32);

        const uint32_t sb = sbase + (uint32_t)(ks % 3) * ST_BYTES;
        #pragma unroll
        for (int t = 0; t < 2; t++) {
            uint32_t bh[4][2], bl[4][2];
            #pragma unroll
            for (int nt = 0; nt < 4; nt++) {
                const int r = wn * 32 + nt * 8 + b_r;
                const int c = t * 2 + b_c;
                const uint32_t so = (uint32_t)(r * 64 + ((c ^ ((r >> 1) & 3)) << 4));
                ldm_x2(bh[nt], sb + 16384 + so);
                ldm_x2(bl[nt], sb + 24576 + so);
            }
            #pragma unroll
            for (int mt = 0; mt < 4; mt++) {
                uint32_t ah[4], al[4];
                const int r = wm * 64 + mt * 16 + a_r;
                const int c = t * 2 + a_c;
                const uint32_t so = (uint32_t)(r * 64 + ((c ^ ((r >> 1) & 3)) << 4));
                ldm_x4(ah, sb + so);
                ldm_x4(al, sb + 8192 + so);
                #pragma unroll
                for (int nt = 0; nt < 4; nt++) {
                    mma16816(acc[mt][nt], ah, bh[nt]);
                    mma16816(acc[mt][nt], ah, bl[nt]);
                    mma16816(acc[mt][nt], al, bh[nt]);
                }
            }
        }
        __syncthreads();
    }

    const int colq = (lane & 3) * 2;
    const int rowq = lane >> 2;
    #pragma unroll
    for (int nt = 0; nt < 4; nt++) {
        const int cg = bn + wn * 32 + nt * 8 + colq;
        const float b0 = bias[cg], b1 = bias[cg + 1];
        #pragma unroll
        for (int mt = 0; mt < 4; mt++) {
            const int r0 = bm + wm * 64 + mt * 16 + rowq;
            const int r1 = r0 + 8;
            float v00 = acc[mt][nt][0] + b0, v01 = acc[mt][nt][1] + b1;
            float v10 = acc[mt][nt][2] + b0, v11 = acc[mt][nt][3] + b1;
            if (MODE == 0) {
                *(float2*)(C + (size_t)r0 * N + cg) = make_float2(v00, v01);
                *(float2*)(C + (size_t)r1 * N + cg) = make_float2(v10, v11);
            } else {
                const int sec = cg >> 10;            // 0=q,1=k,2=v
                const int f  = cg & 1023;
                const int hh = f >> 6, d0 = f & 63;  // d0 even
                #pragma unroll
                for (int rr = 0; rr < 2; rr++) {
                    const int mrow = rr ? r1 : r0;
                    const float va = rr ? v10 : v00;
                    const float vb = rr ? v11 : v01;
                    const int bidx = mrow >> 12;
                    const int ttk  = mrow & (TT - 1);
                    const int bh2  = bidx * NH + hh;
                    const size_t base = ((size_t)bh2 * TT + ttk) * DH + d0;
                    if (sec == 0) {
                        *(float2*)(g_q + base) = make_float2(va, vb);
                    } else {
                        float* dst = (sec == 1) ? g_k : g_v;
                        *(float2*)(dst + base) = make_float2(va, vb);
                        __nv_bfloat162 h2, l2;
                        h2.x = bf_hi(va); h2.y = bf_hi(vb);
                        l2.x = bf_hi(va - __bfloat162float(h2.x));
                        l2.y = bf_hi(vb - __bfloat162float(h2.y));
                        __nv_bfloat162* dh = (sec == 1) ? (__nv_bfloat162*)g_khi
                                                        : (__nv_bfloat162*)g_vhi;
                        __nv_bfloat162* dl = (sec == 1) ? (__nv_bfloat162*)g_klo
                                                        : (__nv_bfloat162*)g_vlo;
                        dh[base >> 1] = h2;
                        dl[base >> 1] = l2;
                    }
                }
            }
        }
    }
}

// ---------------------------------------------------------------------------
// HMMA flash sparse attention (proven R8 structure). CTA = 64 queries x
// (b,h), 8 warps = 4 qgroups x 2 kgroups. Window/global blocks via bf16x3
// MMA; far-stride keys as DIAGONAL blocks through the same cp.async double
// buffer with a cheap SIMT path. Epilogue fused: writes y as bf16 hi/lo
// (replaces the split_y kernel entirely).
// ---------------------------------------------------------------------------
#define AT_QHI   0
#define AT_QLO   8192
#define AT_KV    16384                 // 2 bufs x 32KB
#define AT_MRG   AT_KV                 // merge buffer reuses KV area (16KB)
#define AT_STAT  (AT_KV + 65536)       // 81920: m[64] l[64] pmax[128] psum[128]
#define ATTN3_SMEM (AT_STAT + 384*4)   // 83456

__global__ void __launch_bounds__(256, 2)
attn3()
{
    extern __shared__ __align__(16) unsigned char smb[];
    const uint32_t sb = su32(smb);
    float* stat = (float*)(smb + AT_STAT);   // [0:64) m, [64:128) l
    float* pmax = stat + 128;                // [2][64] (diag: alpha[64])
    float* psum = stat + 256;                // [2][64] (diag: p[64])

    const int tid  = threadIdx.x;
    const int lane = tid & 31;
    const int w    = tid >> 5;
    const int qg   = w >> 1, kg = w & 1;
    const int rbase = qg * 16;
    const int colbase = kg * 32;
    const int q0 = blockIdx.x * 64;
    const int h  = blockIdx.y;
    const int b  = blockIdx.z;
    const int bh = b * NH + h;

    // ---- load Q fp32 -> bf16 hi/lo smem tiles (chunk-swizzled) ----
    {
        const float* qsrc = g_q + ((size_t)bh * TT + q0) * DH;
        #pragma unroll
        for (int it = 0; it < 2; it++) {
            const int id = tid + it * 256;       // 0..511
            const int row = id >> 3, c = id & 7;
            const float4 f0 = *(const float4*)(qsrc + (size_t)row * DH + c * 8);
            const float4 f1 = *(const float4*)(qsrc + (size_t)row * DH + c * 8 + 4);
            float vv[8] = {f0.x, f0.y, f0.z, f0.w, f1.x, f1.y, f1.z, f1.w};
            __nv_bfloat162 hh[4], ll[4];
            #pragma unroll
            for (int u = 0; u < 4; u++) {
                hh[u].x = bf_hi(vv[2*u]);   hh[u].y = bf_hi(vv[2*u+1]);
                ll[u].x = bf_hi(vv[2*u]   - __bfloat162float(hh[u].x));
                ll[u].y = bf_hi(vv[2*u+1] - __bfloat162float(hh[u].y));
            }
            const uint32_t off = (uint32_t)(row * 128 + ((c ^ (row & 7)) << 4));
            *(uint4*)(smb + AT_QHI + off) = *(uint4*)hh;
            *(uint4*)(smb + AT_QLO + off) = *(uint4*)ll;
        }
        if (tid < 64) { stat[tid] = -INFINITY; stat[64 + tid] = 0.f; }
    }

    // ---- block schedule: [global?] + window blocks + diagonal levels ----
    const int kstart = (q0 > 256) ? (q0 - 256) : 0;
    const int extra  = (kstart > 0) ? 1 : 0;
    const int nwin   = extra + (q0 + 64 - kstart) / 64;
    const int ndiag  = (q0 / 128 >= 3) ? (q0 / 128 - 2) : 0;   // levels s=3..
    const int nb     = nwin + ndiag;
    auto kb_of = [&](int bi) -> int {
        if (extra && bi == 0) return 0;
        if (bi < nwin) return kstart + (bi - extra) * 64;
        return q0 - 128 * (bi - nwin + 3);
    };
    auto is_diag = [&](int bi) -> bool { return bi >= nwin; };

    auto load_kv = [&](int bufn, int kb, bool dg) {
        const uint32_t dst0 = sb + AT_KV + (uint32_t)bufn * 32768;
        if (!dg) {
            const size_t gb = ((size_t)bh * TT + kb) * DH;
            const __nv_bfloat16* srcs[4] = {g_khi + gb, g_klo + gb, g_vhi + gb, g_vlo + gb};
            #pragma unroll
            for (int qq = 0; qq < 8; qq++) {
                const int tile = qq >> 1;
                const int within = tid + (qq & 1) * 256;   // 0..511
                const int row = within >> 3, c = within & 7;
                cpa16(dst0 + tile * 8192 + row * 128 + ((c ^ (row & 7)) << 4),
                      srcs[tile] + (size_t)row * DH + c * 8);
            }
        } else {
            const float* ksrc = g_k + ((size_t)bh * TT + kb) * DH;
            const float* vsrc = g_v + ((size_t)bh * TT + kb) * DH;
            #pragma unroll
            for (int qq = 0; qq < 8; qq++) {
                const int id = tid + qq * 256;       // 0..2047
                const int half = id >> 10;           // 0=K 1=V
                const int r = (id >> 4) & 63;
                const int c = id & 15;
                const int cp = c ^ (r & 15);
                const float* src = half ? vsrc : ksrc;
                cpa16(dst0 + half * 16384 + r * 256 + cp * 16,
                      src + (size_t)r * DH + c * 4);
            }
        }
        cpa_commit();
    };

    load_kv(0, kb_of(0), is_diag(0));

    float o[8][4];
    #pragma unroll
    for (int nt = 0; nt < 8; nt++)
        #pragma unroll
        for (int e = 0; e < 4; e++) o[nt][e] = 0.f;

    const int quad_lo = (lane >> 3) & 1;
    const int quad_hi = lane >> 4;
    const int l7 = lane & 7;
    const int rl = rbase + (lane >> 2);    // fragment low row

    __syncthreads();

    for (int bi = 0; bi < nb; bi++) {
        const int kb  = kb_of(bi);
        const int buf = bi & 1;
        const bool dg = is_diag(bi);
        const bool gonly = (extra && bi == 0);

        if (bi + 1 < nb) { load_kv(buf ^ 1, kb_of(bi + 1), is_diag(bi + 1)); cpa_wait<1>(); }
        else             { cpa_wait<0>(); }
        __syncthreads();

        if (dg) {
            // ======== diagonal block: query row r <-> key kb + r ========
            const float* kd = (const float*)(smb + AT_KV + (uint32_t)buf * 32768);
            const float* vd = kd + 4096;
            const int q = lane & 3;
            const int rowi = w * 8 + (lane >> 2);
            float part = 0.f;
            #pragma unroll
            for (int i4 = 0; i4 < 4; i4++) {
                const int ch = 4 * q + i4;
                const float4 k4 = *(const float4*)(kd + rowi * 64 + ((ch ^ (rowi & 15)) << 2));
                const int d0 = q * 16 + i4 * 4;
                const int c8 = d0 >> 3, sub = d0 & 7;
                const uint32_t qoff = (uint32_t)(rowi * 128 + ((c8 ^ (rowi & 7)) << 4) + sub * 2);
                const __nv_bfloat162 qh0 = *(const __nv_bfloat162*)(smb + AT_QHI + qoff);
                const __nv_bfloat162 qh1 = *(const __nv_bfloat162*)(smb + AT_QHI + qoff + 4);
                const __nv_bfloat162 ql0 = *(const __nv_bfloat162*)(smb + AT_QLO + qoff);
                const __nv_bfloat162 ql1 = *(const __nv_bfloat162*)(smb + AT_QLO + qoff + 4);
                part += (__bfloat162float(qh0.x) + __bfloat162float(ql0.x)) * k4.x;
                part += (__bfloat162float(qh0.y) + __bfloat162float(ql0.y)) * k4.y;
                part += (__bfloat162float(qh1.x) + __bfloat162float(ql1.x)) * k4.z;
                part += (__bfloat162float(qh1.y) + __bfloat162float(ql1.y)) * k4.w;
            }
            part += __shfl_xor_sync(0xffffffffu, part, 1);
            part += __shfl_xor_sync(0xffffffffu, part, 2);
            const int j = kb + rowi;
            const float sv = (j >= NGLOB) ? part * 0.125f : -INFINITY;
            if (q == 0) {
                const float mo = stat[rowi];
                const float mn = fmaxf(mo, sv);
                const float alpha = __expf(mo - mn);        // 1 when sv=-inf
                const float p = __expf(sv - mn);            // 0 when sv=-inf
                stat[rowi] = mn;
                stat[64 + rowi] = stat[64 + rowi] * alpha + p;
                pmax[rowi] = alpha;
                psum[rowi] = p;
            }
            __syncthreads();
            const float al0 = pmax[rl], al1 = pmax[rl + 8];
            #pragma unroll
            for (int nt = 0; nt < 8; nt++) {
                o[nt][0] *= al0; o[nt][1] *= al0;
                o[nt][2] *= al1; o[nt][3] *= al1;
            }
            if (kg == 0) {
                #pragma unroll
                for (int rr = 0; rr < 2; rr++) {
                    const int row = rl + rr * 8;
                    const float p = psum[row];
                    #pragma unroll
                    for (int nt = 0; nt < 8; nt++) {
                        #pragma unroll
                        for (int e = 0; e < 2; e++) {
                            const int col = nt * 8 + 2 * (lane & 3) + e;
                            const float vvv = vd[row * 64 + (((col >> 2) ^ (row & 15)) << 2) + (col & 3)];
                            o[nt][rr * 2 + e] += p * vvv;
                        }
                    }
                }
            }
            __syncthreads();
            continue;
        }

        const uint32_t kvb = sb + AT_KV + (uint32_t)buf * 32768;

        // ---- scores: S[16q x 32k] per warp, bf16x3 ----
        float s[4][4];
        #pragma unroll
        for (int nt = 0; nt < 4; nt++)
            #pragma unroll
            for (int e = 0; e < 4; e++) s[nt][e] = 0.f;

        #pragma unroll
        for (int ks = 0; ks < 4; ks++) {
            uint32_t qh[4], ql[4];
            {
                const int row = rbase + quad_lo * 8 + l7;
                const int ch  = 2 * ks + quad_hi;
                const uint32_t off = (uint32_t)(row * 128 + ((ch ^ (row & 7)) << 4));
                ldm_x4(qh, sb + AT_QHI + off);
                ldm_x4(ql, sb + AT_QLO + off);
            }
            #pragma unroll
            for (int ntp = 0; ntp < 2; ntp++) {
                uint32_t kh[4], kl[4];
                const int rowk = colbase + ntp * 16 + quad_hi * 8 + l7;
                const int chk  = 2 * ks + quad_lo;
                const uint32_t offk = (uint32_t)(rowk * 128 + ((chk ^ (rowk & 7)) << 4));
                ldm_x4(kh, kvb + offk);
                ldm_x4(kl, kvb + 8192 + offk);
                mma16816(s[2*ntp],   qh, kh);
                mma16816(s[2*ntp],   qh, kl);
                mma16816(s[2*ntp],   ql, kh);
                mma16816(s[2*ntp+1], qh, kh + 2);
                mma16816(s[2*ntp+1], qh, kl + 2);
                mma16816(s[2*ntp+1], ql, kh + 2);
            }
        }

        // ---- mask + scale ----
        #pragma unroll
        for (int nt = 0; nt < 4; nt++)
            #pragma unroll
            for (int e = 0; e < 4; e++) {
                const int row = rl + (e >> 1) * 8;
                const int i = q0 + row;
                const int j = kb + colbase + nt * 8 + 2 * (lane & 3) + (e & 1);
                const int dij = i - j;
                const bool ok = gonly ? (j < NGLOB)
                    : (dij >= 0 && (dij < WINDOW || (dij & (STRIDE - 1)) == 0 || j < NGLOB));
                s[nt][e] = ok ? s[nt][e] * 0.125f : -INFINITY;
            }

        // ---- partial row max (warp's 32 cols) ----
        float mx0 = fmaxf(fmaxf(s[0][0], s[0][1]), fmaxf(s[1][0], s[1][1]));
        mx0 = fmaxf(mx0, fmaxf(fmaxf(s[2][0], s[2][1]), fmaxf(s[3][0], s[3][1])));
        float mx1 = fmaxf(fmaxf(s[0][2], s[0][3]), fmaxf(s[1][2], s[1][3]));
        mx1 = fmaxf(mx1, fmaxf(fmaxf(s[2][2], s[2][3]), fmaxf(s[3][2], s[3][3])));
        mx0 = fmaxf(mx0, __shfl_xor_sync(0xffffffffu, mx0, 1));
        mx0 = fmaxf(mx0, __shfl_xor_sync(0xffffffffu, mx0, 2));
        mx1 = fmaxf(mx1, __shfl_xor_sync(0xffffffffu, mx1, 1));
        mx1 = fmaxf(mx1, __shfl_xor_sync(0xffffffffu, mx1, 2));
        if ((lane & 3) == 0) {
            pmax[kg * 64 + rl]     = mx0;
            pmax[kg * 64 + rl + 8] = mx1;
        }
        __syncthreads();

        const float m0 = stat[rl], m1 = stat[rl + 8];
        const float mn0 = fmaxf(m0, fmaxf(pmax[rl],     pmax[64 + rl]));
        const float mn1 = fmaxf(m1, fmaxf(pmax[rl + 8], pmax[64 + rl + 8]));
        const float al0 = __expf(m0 - mn0);
        const float al1 = __expf(m1 - mn1);

        float sum0 = 0.f, sum1 = 0.f;
        #pragma unroll
        for (int nt = 0; nt < 4; nt++) {
            s[nt][0] = __expf(s[nt][0] - mn0); sum0 += s[nt][0];
            s[nt][1] = __expf(s[nt][1] - mn0); sum0 += s[nt][1];
            s[nt][2] = __expf(s[nt][2] - mn1); sum1 += s[nt][2];
            s[nt][3] = __expf(s[nt][3] - mn1); sum1 += s[nt][3];
        }
        sum0 += __shfl_xor_sync(0xffffffffu, sum0, 1);
        sum0 += __shfl_xor_sync(0xffffffffu, sum0, 2);
        sum1 += __shfl_xor_sync(0xffffffffu, sum1, 1);
        sum1 += __shfl_xor_sync(0xffffffffu, sum1, 2);
        if ((lane & 3) == 0) {
            psum[kg * 64 + rl]     = sum0;
            psum[kg * 64 + rl + 8] = sum1;
        }
        __syncthreads();

        if (kg == 0 && (lane & 3) == 0) {
            stat[rl] = mn0; stat[rl + 8] = mn1;
            stat[64 + rl]     = stat[64 + rl]     * al0 + psum[rl]     + psum[64 + rl];
            stat[64 + rl + 8] = stat[64 + rl + 8] * al1 + psum[rl + 8] + psum[64 + rl + 8];
        }

        // ---- rescale O ----
        #pragma unroll
        for (int nt = 0; nt < 8; nt++) {
            o[nt][0] *= al0; o[nt][1] *= al0;
            o[nt][2] *= al1; o[nt][3] *= al1;
        }

        // ---- PV: P (hi/lo) x V (hi/lo), 3 combos ----
        #pragma unroll
        for (int ks2 = 0; ks2 < 2; ks2++) {
            const int t0 = 2 * ks2, t1 = t0 + 1;
            uint32_t pah[4], pal[4];
            {
                __nv_bfloat162 h2, l2;
                #pragma unroll
                for (int u = 0; u < 4; u++) {
                    const int tt = (u < 2) ? t0 : t1;
                    const int e0 = (u & 1) * 2;
                    const float p0 = s[tt][e0], p1 = s[tt][e0 + 1];
                    h2.x = bf_hi(p0); h2.y = bf_hi(p1);
                    l2.x = bf_hi(p0 - __bfloat162float(h2.x));
                    l2.y = bf_hi(p1 - __bfloat162float(h2.y));
                    pah[u] = *(uint32_t*)&h2;
                    pal[u] = *(uint32_t*)&l2;
                }
            }
            const int kb2 = colbase + ks2 * 16;
            #pragma unroll
            for (int ntp = 0; ntp < 4; ntp++) {
                uint32_t vh[4], vl[4];
                const int rowv = kb2 + quad_lo * 8 + l7;
                const int chv  = 2 * ntp + quad_hi;
                const uint32_t offv = (uint32_t)(rowv * 128 + ((chv ^ (rowv & 7)) << 4));
                ldm_x4t(vh, kvb + 16384 + offv);
                ldm_x4t(vl, kvb + 24576 + offv);
                mma16816(o[2*ntp],   pah, vh);
                mma16816(o[2*ntp],   pah, vl);
                mma16816(o[2*ntp],   pal, vh);
                mma16816(o[2*ntp+1], pah, vh + 2);
                mma16816(o[2*ntp+1], pah, vl + 2);
                mma16816(o[2*ntp+1], pal, vh + 2);
            }
        }
        __syncthreads();
    }

    // ---- merge partial O: kg0 keeps rows 0-7, kg1 keeps rows 8-15 ----
    float* mrg = (float*)(smb + AT_MRG);   // [qg][16][64]
    {
        const int wr = (kg == 0) ? (lane >> 2) + 8 : (lane >> 2);
        float* basep = mrg + (qg * 16 + wr) * 64;
        const int c0 = kg ? 0 : 2;
        #pragma unroll
        for (int nt = 0; nt < 8; nt++) {
            basep[nt * 8 + 2 * (lane & 3)]     = o[nt][c0];
            basep[nt * 8 + 2 * (lane & 3) + 1] = o[nt][c0 + 1];
        }
    }
    __syncthreads();
    {
        const int rd = (kg == 0) ? (lane >> 2) : (lane >> 2) + 8;
        const float* basep = mrg + (qg * 16 + rd) * 64;
        const int c0 = kg ? 2 : 0;
        #pragma unroll
        for (int nt = 0; nt < 8; nt++) {
            o[nt][c0]     += basep[nt * 8 + 2 * (lane & 3)];
            o[nt][c0 + 1] += basep[nt * 8 + 2 * (lane & 3) + 1];
        }
    }

    // ---- normalize + write y as bf16 hi/lo (replaces split_y kernel) ----
    {
        const int ce0 = kg ? 2 : 0;
        const int row = rbase + (kg ? 8 : 0) + (lane >> 2);
        const float inv = 1.f / stat[64 + row];
        const size_t ybase = ((size_t)(b * TT + q0 + row)) * CB + h * DH;
        #pragma unroll
        for (int nt = 0; nt < 8; nt++) {
            const float v0 = o[nt][ce0] * inv;
            const float v1 = o[nt][ce0 + 1] * inv;
            __nv_bfloat162 h2, l2;
            h2.x = bf_hi(v0); h2.y = bf_hi(v1);
            l2.x = bf_hi(v0 - __bfloat162float(h2.x));
            l2.y = bf_hi(v1 - __bfloat162float(h2.y));
            const size_t idx = (ybase + nt * 8 + 2 * (lane & 3)) >> 1;
            ((__nv_bfloat162*)g_yhi)[idx] = h2;
            ((__nv_bfloat162*)g_ylo)[idx] = l2;
        }
    }
}

// ---------------------------------------------------------------------------
extern "C" void kernel_launch(void* const* d_in, const int* in_sizes, int n_in,
                              void* d_out, int out_size)
{
    (void)in_sizes; (void)n_in; (void)out_size;
    const float* x      = (const float*)d_in[0];
    const float* w_qkv  = (const float*)d_in[1];
    const float* b_qkv  = (const float*)d_in[2];
    const float* w_proj = (const float*)d_in[3];
    const float* b_proj = (const float*)d_in[4];
    float* out = (float*)d_out;

    cudaFuncSetAttribute(tgemm<1>, cudaFuncAttributeMaxDynamicSharedMemorySize, TG_SMEM);
    cudaFuncSetAttribute(tgemm<0>, cudaFuncAttributeMaxDynamicSharedMemorySize, TG_SMEM);
    cudaFuncSetAttribute(attn3,    cudaFuncAttributeMaxDynamicSharedMemorySize, ATTN3_SMEM);

    // 0) bf16 hi/lo splits of activations + transposed weight splits
    split_x<<<(MTOT * CB / 4) / 256, 256>>>((const float4*)x);
    transpose_split<0><<<dim3(N_QKV / 32, CB / 32), dim3(32, 8)>>>(w_qkv, CB, N_QKV);
    transpose_split<1><<<dim3(CB / 32, CB / 32), dim3(32, 8)>>>(w_proj, CB, CB);

    // 1) QKV GEMM -> q/k/v fp32 + k/v bf16 hi/lo
    tgemm<1><<<dim3(N_QKV / 128, MTOT / 128), 256, TG_SMEM>>>(b_qkv, nullptr, N_QKV, CB);

    // 2) HMMA flash sparse attention -> g_yhi/g_ylo (split fused)
    attn3<<<dim3(TT / 64, NH, BBATCH), 256, ATTN3_SMEM>>>();

    // 3) output projection GEMM -> d_out
    tgemm<0><<<dim3(CB / 128, MTOT / 128), 256, TG_SMEM>>>(b_proj, out, CB, CB);
}